// round 15
// baseline (speedup 1.0000x reference)
#include <cuda_runtime.h>
#include <cuda_fp16.h>

#define BB      16
#define CINW    128
#define COUTW   128
#define LPIX    4096
#define KTAP    9
#define XT_ROWS 4352            // 128 zero-pad + 4096 + 128 zero-pad (mult of 8)
#define TILE_N  128
#define NTILES  32              // 4096/128
#define NTHREADS 512            // 16 warps: 4x4 grid of 32x32 warp tiles
#define NSTAGE  4               // TMA ring depth

// 128B rows (64 halfs), XOR-swizzled 16B chunks keyed by (abs_row & 7)
#define ROWB    128
#define TILEB   (128 * ROWB)    // 16384
#define OFF_A   0
#define OFF_B   TILEB
#define STAGE_BYTES (2 * TILEB) // 32768
#define SM_MASK 0               // 9*128 u32 = 4608
#define SM_MBAR 4608            // 4 mbarriers
#define SM_BUF  4736
#define SMEM_TOTAL (SM_BUF + NSTAGE * STAGE_BYTES)   // 135808 (1 CTA/SM)

// ---- global scratch (__device__ arrays: allocation-free rule) ----
// x channel halves: [b][row][128B], chunk c8 of half-channel c stored at (c8 ^ (row&7))
__device__ __align__(16) __half g_xlo[(size_t)BB * XT_ROWS * 64];
__device__ __align__(16) __half g_xhi[(size_t)BB * XT_ROWS * 64];
// weights: 18 contiguous 16KB blocks [(k,ch)][o][128B], swizzled by (o&7)
__device__ __align__(16) __half g_aw[KTAP * 2 * 128 * 64];
__device__ __align__(16) float  g_mterm[(size_t)COUTW * LPIX];

// ================= PTX helpers (baseline ISA, sm_90-level) =================
__device__ __forceinline__ unsigned smem_u32(const void* p) {
    unsigned a;
    asm("{ .reg .u64 t; cvta.to.shared.u64 t, %1; cvt.u32.u64 %0, t; }" : "=r"(a) : "l"(p));
    return a;
}
__device__ __forceinline__ void mbar_init(unsigned addr, unsigned cnt) {
    asm volatile("mbarrier.init.shared.b64 [%0], %1;" :: "r"(addr), "r"(cnt) : "memory");
}
__device__ __forceinline__ void mbar_expect_tx(unsigned addr, unsigned bytes) {
    asm volatile("mbarrier.arrive.expect_tx.shared.b64 _, [%0], %1;"
                 :: "r"(addr), "r"(bytes) : "memory");
}
__device__ __forceinline__ void mbar_wait(unsigned addr, unsigned parity) {
    asm volatile(
        "{\n\t.reg .pred P;\n"
        "WL_%=:\n\t"
        "mbarrier.try_wait.parity.acquire.cta.shared::cta.b64 P, [%0], %1, 0x989680;\n\t"
        "@P bra.uni WD_%=;\n\t"
        "bra.uni WL_%=;\n"
        "WD_%=:\n\t}"
        :: "r"(addr), "r"(parity) : "memory");
}
__device__ __forceinline__ void bulkcp(unsigned dst, const void* src,
                                       unsigned bytes, unsigned mbar) {
    asm volatile(
        "cp.async.bulk.shared::cluster.global.mbarrier::complete_tx::bytes "
        "[%0], [%1], %2, [%3];"
        :: "r"(dst), "l"(src), "r"(bytes), "r"(mbar) : "memory");
}
__device__ __forceinline__ void ldsm4(unsigned* r, unsigned addr) {
    asm volatile("ldmatrix.sync.aligned.m8n8.x4.shared.b16 {%0,%1,%2,%3}, [%4];"
                 : "=r"(r[0]), "=r"(r[1]), "=r"(r[2]), "=r"(r[3]) : "r"(addr));
}
__device__ __forceinline__ void mma16816(float* c, const unsigned* a,
                                         unsigned b0, unsigned b1) {
    asm volatile(
        "mma.sync.aligned.m16n8k16.row.col.f32.f16.f16.f32 "
        "{%0,%1,%2,%3}, {%4,%5,%6,%7}, {%8,%9}, {%0,%1,%2,%3};"
        : "+f"(c[0]), "+f"(c[1]), "+f"(c[2]), "+f"(c[3])
        : "r"(a[0]), "r"(a[1]), "r"(a[2]), "r"(a[3]), "r"(b0), "r"(b1));
}

// ================= fused prep kernel (one launch, 4 disjoint ranges) =================
#define PX_BLKS  8192           // transpose: 128 lg x 4 cg x 16 b
#define PAD_BLKS 128            // 16*256 rows * 8 uint4 / 256
#define PA_BLKS  576            // 147456 / 256
#define PM_BLKS  2048           // 524288 / 256

__global__ void prep_all_kernel(const float* __restrict__ x,
                                const float* __restrict__ w,
                                const float* __restrict__ mask,
                                const float* __restrict__ mw,
                                const float* __restrict__ bias) {
    __shared__ float sm[32][33];
    int bx = blockIdx.x;
    int tid = threadIdx.x;

    if (bx < PX_BLKS) {
        // ---- x[b][c][l] fp32 -> g_x{lo,hi}[b][128+l][c%64] fp16, swizzled ----
        int b = bx >> 9, cg = (bx >> 7) & 3, lg = bx & 127;
        int lr = tid & 31, cr = tid >> 5;
        #pragma unroll
        for (int r = 0; r < 4; r++) {
            int c = cg * 32 + cr + r * 8;
            sm[cr + r * 8][lr] = x[((size_t)(b * CINW + c)) * LPIX + lg * 32 + lr];
        }
        __syncthreads();
        #pragma unroll
        for (int r = 0; r < 4; r++) {
            int lrow = cr + r * 8;
            size_t rowidx = (size_t)b * XT_ROWS + 128 + lg * 32 + lrow;
            int c = cg * 32 + lr;
            __half* dst = (c < 64) ? g_xlo : g_xhi;
            int c6 = c & 63;
            unsigned off = ((((unsigned)(c6 >> 3)) ^ ((unsigned)rowidx & 7u)) << 4)
                         | ((unsigned)(c6 & 7) * 2);
            *(__half*)((char*)dst + rowidx * ROWB + off) = __float2half_rn(sm[lr][lrow]);
        }
    } else if (bx < PX_BLKS + PAD_BLKS) {
        // ---- zero the 128-row pads (both halves; zeros swizzle to zeros) ----
        int t = (bx - PX_BLKS) * 256 + tid;       // 16 b * 256 rows * 8 chunks
        int c16 = t & 7;
        int pr = (t >> 3) & 255;
        int b = t >> 11;
        int row = (pr < 128) ? pr : (pr + 4096);
        size_t off = ((size_t)b * XT_ROWS + row) * ROWB + c16 * 16;
        *(uint4*)((char*)g_xlo + off) = make_uint4(0, 0, 0, 0);
        *(uint4*)((char*)g_xhi + off) = make_uint4(0, 0, 0, 0);
    } else if (bx < PX_BLKS + PAD_BLKS + PA_BLKS) {
        // ---- weight[o][cin][k] -> g_aw[(k,ch)][o][c6], swizzled by (o&7) ----
        int idx = (bx - PX_BLKS - PAD_BLKS) * 256 + tid;
        if (idx < COUTW * CINW * KTAP) {
            int k = idx % KTAP;
            int cin = (idx / KTAP) % CINW;
            int o = idx / (KTAP * CINW);
            int ch = cin >> 6, c6 = cin & 63;
            unsigned off = ((((unsigned)(c6 >> 3)) ^ ((unsigned)o & 7u)) << 4)
                         | ((unsigned)(c6 & 7) * 2);
            *(__half*)((char*)g_aw + (size_t)(k * 2 + ch) * TILEB
                       + (size_t)o * ROWB + off) = __float2half_rn(w[idx]);
        }
    } else {
        // ---- mterm[o][l] = bias[o] + sum_k mw[o][k]*mask[k][l] ----
        int idx = (bx - PX_BLKS - PAD_BLKS - PA_BLKS) * 256 + tid;
        if (idx < COUTW * LPIX) {
            int o = idx >> 12, l = idx & 4095;
            float s = bias[o];
            #pragma unroll
            for (int k = 0; k < KTAP; k++)
                s += mw[o * KTAP + k] * mask[k * LPIX + l];
            g_mterm[idx] = s;
        }
    }
}

// ================= main tensor-core kernel (16 warps, 32x32 tiles, 4-deep ring) ====
__global__ void __launch_bounds__(NTHREADS, 1)
lmconv_mma_kernel(const float* __restrict__ mask, float* __restrict__ out) {
    extern __shared__ char smem[];
    unsigned sb = smem_u32(smem);
    const int tid = threadIdx.x, wid = tid >> 5, lane = tid & 31;
    const int b = blockIdx.y, l0 = blockIdx.x * TILE_N;
    const int wm = wid >> 2, wn = wid & 3;       // 4x4 warp grid, 32M x 32N each

    unsigned* mS = (unsigned*)(smem + SM_MASK);

    // per-tile mask select words (w-edge wrap folded in)
    for (int j = tid; j < KTAP * TILE_N; j += NTHREADS) {
        int k = j >> 7, n = j & 127;
        int l = l0 + n;
        float mv = mask[k * LPIX + l];
        int dx = k % 3 - 1;
        bool m = (mv != 0.0f);
        if (dx == 1  && (l & 63) == 63) m = false;
        if (dx == -1 && (l & 63) == 0)  m = false;
        mS[j] = m ? 0xFFFFFFFFu : 0u;
    }

    if (tid < NSTAGE) mbar_init(sb + SM_MBAR + tid * 8, 1);
    __syncthreads();                             // mbars + mask words visible

    auto issue = [&](int i) {                    // 2 bulk copies per K=64 stage
        int k = i >> 1, ch = i & 1, s = i & (NSTAGE - 1);
        unsigned mb  = sb + SM_MBAR + (unsigned)(s * 8);
        unsigned buf = sb + SM_BUF + (unsigned)(s * STAGE_BYTES);
        mbar_expect_tx(mb, STAGE_BYTES);
        bulkcp(buf + OFF_A, (const char*)g_aw + (size_t)(k * 2 + ch) * TILEB, TILEB, mb);
        int dlt = (k / 3 - 1) * 64 + (k % 3 - 1);
        size_t row = (size_t)b * XT_ROWS + 128 + l0 + dlt;
        const __half* src = ch ? g_xhi : g_xlo;
        bulkcp(buf + OFF_B, (const char*)src + row * ROWB, TILEB, mb);
    };

    if (tid == 0) { issue(0); issue(1); issue(2); }

    float acc[2][4][4];
    #pragma unroll
    for (int im = 0; im < 2; im++)
        #pragma unroll
        for (int jn = 0; jn < 4; jn++)
            #pragma unroll
            for (int q = 0; q < 4; q++) acc[im][jn][q] = 0.0f;

    const int lrow = lane & 15;                  // fragment row in 16-row block
    const int hi   = lane >> 4;                  // 16B chunk half-select
    const int kxa  = lrow & 7;                   // A swizzle key ((wm*32+lrow)&7)
    const unsigned aRow = (unsigned)((wm * 32 + lrow) * ROWB);
    const unsigned bRow = (unsigned)((wn * 32 + lrow) * ROWB);
    const int mrow = lane >> 2;                  // mask row in 8-row block

    #pragma unroll 1
    for (int i = 0; i < 2 * KTAP; i++) {
        int s = i & (NSTAGE - 1);
        mbar_wait(sb + SM_MBAR + (unsigned)(s * 8), (i >> 2) & 1);
        __syncthreads();                         // all warps past compute(i-1)
        if (i + 3 < 2 * KTAP && tid == 0) issue(i + 3);

        unsigned base = sb + SM_BUF + (unsigned)(s * STAGE_BYTES);
        const int k = i >> 1;
        int dlt = (k / 3 - 1) * 64 + (k % 3 - 1);
        const int kxb = (lrow + dlt) & 7;        // B swizzle key (abs row & 7)

        unsigned mw0[2], mw1[2];
        #pragma unroll
        for (int nb = 0; nb < 2; nb++) {
            mw0[nb] = mS[k * TILE_N + wn * 32 + nb * 16 + mrow];
            mw1[nb] = mS[k * TILE_N + wn * 32 + nb * 16 + 8 + mrow];
        }

        #pragma unroll
        for (int ks = 0; ks < 4; ks++) {         // K=64 per stage, 16 per step
            int ci = ks * 2 + hi;
            unsigned aoff = (unsigned)((ci ^ kxa) << 4);
            unsigned boff = (unsigned)((ci ^ kxb) << 4);
            unsigned a[2][4];
            #pragma unroll
            for (int im = 0; im < 2; im++)
                ldsm4(a[im], base + OFF_A + aRow + (unsigned)(im * 16 * ROWB) + aoff);
            unsigned bf[2][4];
            #pragma unroll
            for (int nb = 0; nb < 2; nb++) {
                ldsm4(bf[nb], base + OFF_B + bRow + (unsigned)(nb * 16 * ROWB) + boff);
                bf[nb][0] &= mw0[nb]; bf[nb][2] &= mw0[nb];
                bf[nb][1] &= mw1[nb]; bf[nb][3] &= mw1[nb];
            }
            #pragma unroll
            for (int im = 0; im < 2; im++)
                #pragma unroll
                for (int nb = 0; nb < 2; nb++) {
                    mma16816(acc[im][2 * nb + 0], a[im], bf[nb][0], bf[nb][2]);
                    mma16816(acc[im][2 * nb + 1], a[im], bf[nb][1], bf[nb][3]);
                }
        }
    }

    // ---- epilogue: add mterm, store float2 ----
    #pragma unroll
    for (int im = 0; im < 2; im++) {
        #pragma unroll
        for (int jn = 0; jn < 4; jn++) {
            int row0 = wm * 32 + im * 16 + (lane >> 2);
            int col = wn * 32 + jn * 8 + (lane & 3) * 2;
            int l = l0 + col;
            {
                const float2 mt = *(const float2*)&g_mterm[(size_t)row0 * LPIX + l];
                float2 v;
                v.x = acc[im][jn][0] + mt.x;
                v.y = acc[im][jn][1] + mt.y;
                *(float2*)&out[((size_t)(b * COUTW + row0)) * LPIX + l] = v;
            }
            {
                int row1 = row0 + 8;
                const float2 mt = *(const float2*)&g_mterm[(size_t)row1 * LPIX + l];
                float2 v;
                v.x = acc[im][jn][2] + mt.x;
                v.y = acc[im][jn][3] + mt.y;
                *(float2*)&out[((size_t)(b * COUTW + row1)) * LPIX + l] = v;
            }
        }
    }
}

// ================= launch =================
extern "C" void kernel_launch(void* const* d_in, const int* in_sizes, int n_in,
                              void* d_out, int out_size) {
    const float* x    = (const float*)d_in[0];   // (16,128,64,64)
    const float* mask = (const float*)d_in[1];   // (1,9,4096)
    const float* w    = (const float*)d_in[2];   // (128,128,3,3)
    const float* mw   = (const float*)d_in[3];   // (128,3,3)
    const float* bias = (const float*)d_in[4];   // (128,)
    float* out = (float*)d_out;                  // (16,128,64,64)

    cudaFuncSetAttribute(lmconv_mma_kernel,
                         cudaFuncAttributeMaxDynamicSharedMemorySize, SMEM_TOTAL);

    prep_all_kernel<<<PX_BLKS + PAD_BLKS + PA_BLKS + PM_BLKS, 256>>>(x, w, mask, mw, bias);

    lmconv_mma_kernel<<<dim3(NTILES, BB), NTHREADS, SMEM_TOTAL>>>(mask, out);
}

// round 16
// speedup vs baseline: 1.3651x; 1.3651x over previous
#include <cuda_runtime.h>
#include <cuda_fp16.h>

#define BB      16
#define CINW    128
#define COUTW   128
#define LPIX    4096
#define KTAP    9
#define XT_ROWS 4352            // 128 zero-pad + 4096 + 128 zero-pad (mult of 8)
#define TILE_N  64
#define NTILES  64              // 4096/64
#define NTHREADS 256            // 8 warps: 4x2 grid of 32x32 warp tiles

// 128B rows (64 halfs), XOR-swizzled 16B chunks keyed by (abs_row & 7)
#define ROWB    128
#define A_TILEB (128 * ROWB)    // 16384
#define B_TILEB (64 * ROWB)     // 8192
#define OFF_A   0
#define OFF_B   A_TILEB
#define STAGE_BYTES (A_TILEB + B_TILEB)   // 24576
#define SM_MASK 0               // 9*64 u32 = 2304
#define SM_MBAR 2304            // 2 mbarriers
#define SM_BUF  2432
#define SMEM_TOTAL (SM_BUF + 2 * STAGE_BYTES)   // 51584 -> 3 CTAs/SM

// ---- global scratch (__device__ arrays: allocation-free rule) ----
// x channel halves: [b][row][128B], chunk c8 of half-channel c stored at (c8 ^ (row&7))
__device__ __align__(16) __half g_xlo[(size_t)BB * XT_ROWS * 64];
__device__ __align__(16) __half g_xhi[(size_t)BB * XT_ROWS * 64];
// weights: 18 contiguous 16KB blocks [(k,ch)][o][128B], swizzled by (o&7)
__device__ __align__(16) __half g_aw[KTAP * 2 * 128 * 64];
__device__ __align__(16) float  g_mterm[(size_t)COUTW * LPIX];

// ================= PTX helpers (baseline ISA, sm_90-level) =================
__device__ __forceinline__ unsigned smem_u32(const void* p) {
    unsigned a;
    asm("{ .reg .u64 t; cvta.to.shared.u64 t, %1; cvt.u32.u64 %0, t; }" : "=r"(a) : "l"(p));
    return a;
}
__device__ __forceinline__ void mbar_init(unsigned addr, unsigned cnt) {
    asm volatile("mbarrier.init.shared.b64 [%0], %1;" :: "r"(addr), "r"(cnt) : "memory");
}
__device__ __forceinline__ void mbar_expect_tx(unsigned addr, unsigned bytes) {
    asm volatile("mbarrier.arrive.expect_tx.shared.b64 _, [%0], %1;"
                 :: "r"(addr), "r"(bytes) : "memory");
}
__device__ __forceinline__ void mbar_wait(unsigned addr, unsigned parity) {
    asm volatile(
        "{\n\t.reg .pred P;\n"
        "WL_%=:\n\t"
        "mbarrier.try_wait.parity.acquire.cta.shared::cta.b64 P, [%0], %1, 0x989680;\n\t"
        "@P bra.uni WD_%=;\n\t"
        "bra.uni WL_%=;\n"
        "WD_%=:\n\t}"
        :: "r"(addr), "r"(parity) : "memory");
}
__device__ __forceinline__ void bulkcp(unsigned dst, const void* src,
                                       unsigned bytes, unsigned mbar) {
    asm volatile(
        "cp.async.bulk.shared::cluster.global.mbarrier::complete_tx::bytes "
        "[%0], [%1], %2, [%3];"
        :: "r"(dst), "l"(src), "r"(bytes), "r"(mbar) : "memory");
}
__device__ __forceinline__ void ldsm4(unsigned* r, unsigned addr) {
    asm volatile("ldmatrix.sync.aligned.m8n8.x4.shared.b16 {%0,%1,%2,%3}, [%4];"
                 : "=r"(r[0]), "=r"(r[1]), "=r"(r[2]), "=r"(r[3]) : "r"(addr));
}
__device__ __forceinline__ void mma16816(float* c, const unsigned* a,
                                         unsigned b0, unsigned b1) {
    asm volatile(
        "mma.sync.aligned.m16n8k16.row.col.f32.f16.f16.f32 "
        "{%0,%1,%2,%3}, {%4,%5,%6,%7}, {%8,%9}, {%0,%1,%2,%3};"
        : "+f"(c[0]), "+f"(c[1]), "+f"(c[2]), "+f"(c[3])
        : "r"(a[0]), "r"(a[1]), "r"(a[2]), "r"(a[3]), "r"(b0), "r"(b1));
}

// ================= fused prep kernel (one launch, 4 disjoint ranges) =================
#define PX_BLKS  8192           // transpose: 128 lg x 4 cg x 16 b
#define PAD_BLKS 128            // 16*256 rows * 8 uint4 / 256
#define PA_BLKS  576            // 147456 / 256
#define PM_BLKS  2048           // 524288 / 256

__global__ void prep_all_kernel(const float* __restrict__ x,
                                const float* __restrict__ w,
                                const float* __restrict__ mask,
                                const float* __restrict__ mw,
                                const float* __restrict__ bias) {
    __shared__ float sm[32][33];
    int bx = blockIdx.x;
    int tid = threadIdx.x;

    if (bx < PX_BLKS) {
        // ---- x[b][c][l] fp32 -> g_x{lo,hi}[b][128+l][c%64] fp16, swizzled ----
        int b = bx >> 9, cg = (bx >> 7) & 3, lg = bx & 127;
        int lr = tid & 31, cr = tid >> 5;
        #pragma unroll
        for (int r = 0; r < 4; r++) {
            int c = cg * 32 + cr + r * 8;
            sm[cr + r * 8][lr] = x[((size_t)(b * CINW + c)) * LPIX + lg * 32 + lr];
        }
        __syncthreads();
        #pragma unroll
        for (int r = 0; r < 4; r++) {
            int lrow = cr + r * 8;
            size_t rowidx = (size_t)b * XT_ROWS + 128 + lg * 32 + lrow;
            int c = cg * 32 + lr;
            __half* dst = (c < 64) ? g_xlo : g_xhi;
            int c6 = c & 63;
            unsigned off = ((((unsigned)(c6 >> 3)) ^ ((unsigned)rowidx & 7u)) << 4)
                         | ((unsigned)(c6 & 7) * 2);
            *(__half*)((char*)dst + rowidx * ROWB + off) = __float2half_rn(sm[lr][lrow]);
        }
    } else if (bx < PX_BLKS + PAD_BLKS) {
        // ---- zero the 128-row pads (both halves; zeros swizzle to zeros) ----
        int t = (bx - PX_BLKS) * 256 + tid;       // 16 b * 256 rows * 8 chunks
        int c16 = t & 7;
        int pr = (t >> 3) & 255;
        int b = t >> 11;
        int row = (pr < 128) ? pr : (pr + 4096);
        size_t off = ((size_t)b * XT_ROWS + row) * ROWB + c16 * 16;
        *(uint4*)((char*)g_xlo + off) = make_uint4(0, 0, 0, 0);
        *(uint4*)((char*)g_xhi + off) = make_uint4(0, 0, 0, 0);
    } else if (bx < PX_BLKS + PAD_BLKS + PA_BLKS) {
        // ---- weight[o][cin][k] -> g_aw[(k,ch)][o][c6], swizzled by (o&7) ----
        int idx = (bx - PX_BLKS - PAD_BLKS) * 256 + tid;
        if (idx < COUTW * CINW * KTAP) {
            int k = idx % KTAP;
            int cin = (idx / KTAP) % CINW;
            int o = idx / (KTAP * CINW);
            int ch = cin >> 6, c6 = cin & 63;
            unsigned off = ((((unsigned)(c6 >> 3)) ^ ((unsigned)o & 7u)) << 4)
                         | ((unsigned)(c6 & 7) * 2);
            *(__half*)((char*)g_aw + (size_t)(k * 2 + ch) * A_TILEB
                       + (size_t)o * ROWB + off) = __float2half_rn(w[idx]);
        }
    } else {
        // ---- mterm[o][l] = bias[o] + sum_k mw[o][k]*mask[k][l] ----
        int idx = (bx - PX_BLKS - PAD_BLKS - PA_BLKS) * 256 + tid;
        if (idx < COUTW * LPIX) {
            int o = idx >> 12, l = idx & 4095;
            float s = bias[o];
            #pragma unroll
            for (int k = 0; k < KTAP; k++)
                s += mw[o * KTAP + k] * mask[k * LPIX + l];
            g_mterm[idx] = s;
        }
    }
}

// ======== main tensor-core kernel (8 warps, 32x32 tiles, 3 CTAs/SM) ========
__global__ void __launch_bounds__(NTHREADS, 3)
lmconv_mma_kernel(const float* __restrict__ mask, float* __restrict__ out) {
    extern __shared__ char smem[];
    unsigned sb = smem_u32(smem);
    const int tid = threadIdx.x, wid = tid >> 5, lane = tid & 31;
    const int b = blockIdx.y, l0 = blockIdx.x * TILE_N;
    const int wm = wid >> 1, wn = wid & 1;       // 4x2 warp grid, 32M x 32N each

    unsigned* mS = (unsigned*)(smem + SM_MASK);

    // per-tile mask select words (w-edge wrap folded in); strided (576 > 256!)
    for (int j = tid; j < KTAP * TILE_N; j += NTHREADS) {
        int k = j >> 6, n = j & 63;
        int l = l0 + n;
        float mv = mask[k * LPIX + l];
        int dx = k % 3 - 1;
        bool m = (mv != 0.0f);
        if (dx == 1  && (l & 63) == 63) m = false;
        if (dx == -1 && (l & 63) == 0)  m = false;
        mS[j] = m ? 0xFFFFFFFFu : 0u;
    }

    if (tid < 2) mbar_init(sb + SM_MBAR + tid * 8, 1);
    __syncthreads();                             // mbars + mask words visible

    auto issue = [&](int i) {                    // 2 bulk copies per K=64 stage
        int k = i >> 1, ch = i & 1, s = i & 1;
        unsigned mb  = sb + SM_MBAR + (unsigned)(s * 8);
        unsigned buf = sb + SM_BUF + (unsigned)(s * STAGE_BYTES);
        mbar_expect_tx(mb, STAGE_BYTES);
        bulkcp(buf + OFF_A, (const char*)g_aw + (size_t)(k * 2 + ch) * A_TILEB,
               A_TILEB, mb);
        int dlt = (k / 3 - 1) * 64 + (k % 3 - 1);
        size_t row = (size_t)b * XT_ROWS + 128 + l0 + dlt;
        const __half* src = ch ? g_xhi : g_xlo;
        bulkcp(buf + OFF_B, (const char*)src + row * ROWB, B_TILEB, mb);
    };

    if (tid == 0) issue(0);

    float acc[2][4][4];
    #pragma unroll
    for (int im = 0; im < 2; im++)
        #pragma unroll
        for (int jn = 0; jn < 4; jn++)
            #pragma unroll
            for (int q = 0; q < 4; q++) acc[im][jn][q] = 0.0f;

    const int lrow = lane & 15;                  // fragment row in 16-row block
    const int hi   = lane >> 4;                  // 16B chunk half-select
    const int kxa  = lrow & 7;                   // A swizzle key ((wm*32+lrow)&7)
    const unsigned aRow = (unsigned)((wm * 32 + lrow) * ROWB);
    const unsigned bRow = (unsigned)((wn * 32 + lrow) * ROWB);
    const int mrow = lane >> 2;                  // mask row in 8-row block

    #pragma unroll 1
    for (int i = 0; i < 2 * KTAP; i++) {
        int s = i & 1;
        mbar_wait(sb + SM_MBAR + (unsigned)(s * 8), (i >> 1) & 1);
        __syncthreads();                         // all warps past compute(i-1)
        if (i + 1 < 2 * KTAP && tid == 0) issue(i + 1);

        unsigned base = sb + SM_BUF + (unsigned)(s * STAGE_BYTES);
        const int k = i >> 1;
        int dlt = (k / 3 - 1) * 64 + (k % 3 - 1);
        const int kxb = (lrow + dlt) & 7;        // B swizzle key (abs row & 7)

        unsigned mw0[2], mw1[2];
        #pragma unroll
        for (int nb = 0; nb < 2; nb++) {
            mw0[nb] = mS[k * TILE_N + wn * 32 + nb * 16 + mrow];
            mw1[nb] = mS[k * TILE_N + wn * 32 + nb * 16 + 8 + mrow];
        }

        #pragma unroll
        for (int ks = 0; ks < 4; ks++) {         // K=64 per stage, 16 per step
            int ci = ks * 2 + hi;
            unsigned aoff = (unsigned)((ci ^ kxa) << 4);
            unsigned boff = (unsigned)((ci ^ kxb) << 4);
            unsigned a[2][4];
            #pragma unroll
            for (int im = 0; im < 2; im++)
                ldsm4(a[im], base + OFF_A + aRow + (unsigned)(im * 16 * ROWB) + aoff);
            unsigned bf[2][4];
            #pragma unroll
            for (int nb = 0; nb < 2; nb++) {
                ldsm4(bf[nb], base + OFF_B + bRow + (unsigned)(nb * 16 * ROWB) + boff);
                bf[nb][0] &= mw0[nb]; bf[nb][2] &= mw0[nb];
                bf[nb][1] &= mw1[nb]; bf[nb][3] &= mw1[nb];
            }
            #pragma unroll
            for (int im = 0; im < 2; im++)
                #pragma unroll
                for (int nb = 0; nb < 2; nb++) {
                    mma16816(acc[im][2 * nb + 0], a[im], bf[nb][0], bf[nb][2]);
                    mma16816(acc[im][2 * nb + 1], a[im], bf[nb][1], bf[nb][3]);
                }
        }
    }

    // ---- epilogue: add mterm, store float2 ----
    #pragma unroll
    for (int im = 0; im < 2; im++) {
        #pragma unroll
        for (int jn = 0; jn < 4; jn++) {
            int row0 = wm * 32 + im * 16 + (lane >> 2);
            int col = wn * 32 + jn * 8 + (lane & 3) * 2;
            int l = l0 + col;
            {
                const float2 mt = *(const float2*)&g_mterm[(size_t)row0 * LPIX + l];
                float2 v;
                v.x = acc[im][jn][0] + mt.x;
                v.y = acc[im][jn][1] + mt.y;
                *(float2*)&out[((size_t)(b * COUTW + row0)) * LPIX + l] = v;
            }
            {
                int row1 = row0 + 8;
                const float2 mt = *(const float2*)&g_mterm[(size_t)row1 * LPIX + l];
                float2 v;
                v.x = acc[im][jn][2] + mt.x;
                v.y = acc[im][jn][3] + mt.y;
                *(float2*)&out[((size_t)(b * COUTW + row1)) * LPIX + l] = v;
            }
        }
    }
}

// ================= launch =================
extern "C" void kernel_launch(void* const* d_in, const int* in_sizes, int n_in,
                              void* d_out, int out_size) {
    const float* x    = (const float*)d_in[0];   // (16,128,64,64)
    const float* mask = (const float*)d_in[1];   // (1,9,4096)
    const float* w    = (const float*)d_in[2];   // (128,128,3,3)
    const float* mw   = (const float*)d_in[3];   // (128,3,3)
    const float* bias = (const float*)d_in[4];   // (128,)
    float* out = (float*)d_out;                  // (16,128,64,64)

    cudaFuncSetAttribute(lmconv_mma_kernel,
                         cudaFuncAttributeMaxDynamicSharedMemorySize, SMEM_TOTAL);
    cudaFuncSetAttribute(lmconv_mma_kernel,
                         cudaFuncAttributePreferredSharedMemoryCarveout, 100);

    prep_all_kernel<<<PX_BLKS + PAD_BLKS + PA_BLKS + PM_BLKS, 256>>>(x, w, mask, mw, bias);

    lmconv_mma_kernel<<<dim3(NTILES, BB), NTHREADS, SMEM_TOTAL>>>(mask, out);
}